// round 8
// baseline (speedup 1.0000x reference)
#include <cuda_runtime.h>
#include <cuda_fp16.h>
#include <cstdint>

#define BB 8
#define NN 16384
#define FF 64
#define EE 262144
#define CC 10
#define BN_EPS 1e-5f

// ---------------- device scratch (no allocs; zero-initialized at load) ----------------
__device__ int    g_deg_out[BB * NN];
__device__ int    g_deg_in [BB * NN];
__device__ int    g_cursor [BB * NN];
__device__ float  g_rs_out [BB * NN];
__device__ float  g_rs_in  [BB * NN];
__device__ int    g_row_off[BB * (NN + 1)];
__device__ __align__(16) int   g_esrt[(size_t)BB * EE];
__device__ __align__(16) float g_xs [(size_t)BB * NN * FF];
__device__ __align__(16) float g_h1 [(size_t)BB * NN * FF];
__device__ __align__(16) float g_h2 [(size_t)BB * NN * FF];
__device__ float  g_bn_sum [2 * FF];
__device__ float  g_bn_coef[2 * FF];

// ---------------- f32x2 helpers ----------------
__device__ __forceinline__ unsigned long long pk2(float lo, float hi) {
    unsigned long long r;
    asm("mov.b64 %0, {%1, %2};" : "=l"(r) : "f"(lo), "f"(hi));
    return r;
}
__device__ __forceinline__ void upk2(unsigned long long v, float& lo, float& hi) {
    asm("mov.b64 {%0, %1}, %2;" : "=f"(lo), "=f"(hi) : "l"(v));
}
__device__ __forceinline__ unsigned long long fma2(unsigned long long a,
                                                   unsigned long long b,
                                                   unsigned long long c) {
    unsigned long long d;
    asm("fma.rn.f32x2 %0, %1, %2, %3;" : "=l"(d) : "l"(a), "l"(b), "l"(c));
    return d;
}

// ---------------- preprocessing ----------------

__global__ void k_degree(const int4* __restrict__ src4, const int4* __restrict__ dst4) {
    int i = blockIdx.x * blockDim.x + threadIdx.x;   // BB*EE/4 = 512K
    int4 s = __ldg(src4 + i);
    int4 d = __ldg(dst4 + i);
    int base = (i >> 16) * NN;                        // 65536 int4 per batch
    atomicAdd(&g_deg_out[base + s.x], 1);
    atomicAdd(&g_deg_out[base + s.y], 1);
    atomicAdd(&g_deg_out[base + s.z], 1);
    atomicAdd(&g_deg_out[base + s.w], 1);
    atomicAdd(&g_deg_in[base + d.x], 1);
    atomicAdd(&g_deg_in[base + d.y], 1);
    atomicAdd(&g_deg_in[base + d.z], 1);
    atomicAdd(&g_deg_in[base + d.w], 1);
}

__global__ __launch_bounds__(1024) void k_scan() {
    __shared__ int warpsum[32];
    int b = blockIdx.x, t = threadIdx.x;
    int lane = t & 31, wid = t >> 5;
    int base = b * NN + t * 16;
    int loc[16];
    int sum = 0;
#pragma unroll
    for (int i = 0; i < 16; i++) {
        int d = g_deg_in[base + i];
        loc[i] = sum; sum += d;
        g_rs_in[base + i] = rsqrtf((float)(d < 1 ? 1 : d));
        int dgo = g_deg_out[base + i];
        g_rs_out[base + i] = rsqrtf((float)(dgo < 1 ? 1 : dgo));
        g_deg_in[base + i]  = 0;
        g_deg_out[base + i] = 0;
    }
    int v = sum;
#pragma unroll
    for (int off = 1; off < 32; off <<= 1) {
        int u = __shfl_up_sync(0xFFFFFFFFu, v, off);
        if (lane >= off) v += u;
    }
    if (lane == 31) warpsum[wid] = v;
    __syncthreads();
    if (wid == 0) {
        int w = warpsum[lane];
#pragma unroll
        for (int off = 1; off < 32; off <<= 1) {
            int u = __shfl_up_sync(0xFFFFFFFFu, w, off);
            if (lane >= off) w += u;
        }
        warpsum[lane] = w;
    }
    __syncthreads();
    int wbase = (wid == 0) ? 0 : warpsum[wid - 1];
    int excl  = wbase + v - sum;
    int ob = b * (NN + 1) + t * 16;
#pragma unroll
    for (int i = 0; i < 16; i++) {
        int o = excl + loc[i];
        g_row_off[ob + i] = o;
        g_cursor[base + i] = o;
    }
    if (t == 1023) g_row_off[b * (NN + 1) + NN] = excl + sum;
}

__global__ void k_fill(const int4* __restrict__ src4, const int4* __restrict__ dst4,
                       const float4* __restrict__ x4) {
    int i = blockIdx.x * blockDim.x + threadIdx.x;   // 512K
    int b = i >> 16;
    int4 s = __ldg(src4 + i);
    int4 d = __ldg(dst4 + i);
    int cb = b * NN;
    size_t eb = (size_t)b * EE;
    int p0 = atomicAdd(&g_cursor[cb + d.x], 1);
    int p1 = atomicAdd(&g_cursor[cb + d.y], 1);
    int p2 = atomicAdd(&g_cursor[cb + d.z], 1);
    int p3 = atomicAdd(&g_cursor[cb + d.w], 1);
    g_esrt[eb + p0] = s.x;
    g_esrt[eb + p1] = s.y;
    g_esrt[eb + p2] = s.z;
    g_esrt[eb + p3] = s.w;
#pragma unroll
    for (int j = 0; j < 4; j++) {
        int fi = i * 4 + j;
        float sc = g_rs_out[fi >> 4];
        float4 v = __ldg(x4 + fi);
        v.x *= sc; v.y *= sc; v.z *= sc; v.w *= sc;
        ((float4*)g_xs)[fi] = v;
    }
}

// ---------------- fused conv: gather + GEMM ----------------
// 1024 threads, 256 nodes/CTA.
// Gather: warp-per-node (8 rounds), lane handles feats {2l, 2l+1} (float2): 2 wf/edge,
//         int4 broadcast index loads. Result -> swizzled sT[n][k] (float2 STS).
// GEMM:   warp = 16n x 32f tile, thread = 4n x 4f, both operands LDS.128 with XOR
//         swizzle (conflict-free), packed fma.rn.f32x2 accumulation.
// smem layout (dynamic): sT [256*64] floats @0, sWt [64*64] floats @65536B.

#define SMEM_CONV (256 * 64 * 4 + 64 * 64 * 4)

__global__ __launch_bounds__(1024, 1) void k_conv(const float* __restrict__ W,
                                                  const float* __restrict__ bias,
                                                  int phase) {
    extern __shared__ float smf[];
    float* sT  = smf;                                 // [256][64] swizzled
    float* sWt = smf + 256 * 64;                      // [64][64]  swizzled, transposed

    const float* in  = phase ? g_h1 : g_xs;
    float*       out = phase ? g_h2 : g_h1;

    int t = threadIdx.x, w = t >> 5, lane = t & 31;
    int cb = blockIdx.x;
    int b  = cb >> 6;                                 // 64 CTAs per batch
    int n0 = (cb & 63) << 8;                          // 256 nodes per CTA

    // ---- W transpose -> sWt[q][k ^ sw] ----
#pragma unroll
    for (int i = 0; i < 4; i++) {
        int idx = t + i * 1024;                       // 4096
        int k = idx >> 6, q = idx & 63;
        sWt[q * 64 + (k ^ (((q >> 2) & 7) << 2))] = __ldg(W + idx);
    }

    // ---- gather: warp w, rounds r: node m = w*8+r ----
    {
        const float2* inb = (const float2*)(in + (size_t)b * NN * FF);
        const int*    es  = g_esrt + (size_t)b * EE;
        const int*    ro  = g_row_off + b * (NN + 1) + n0;
        int fl = lane;                                // feat pair index: feats 2l,2l+1
#pragma unroll 1
        for (int r = 0; r < 8; r++) {
            int m = w * 8 + r;
            int e  = ro[m];
            int r1 = ro[m + 1];
            float a0 = 0.f, a1 = 0.f;
            for (; e < r1 && (e & 3); e++) {
                int s0 = __ldg(es + e);
                float2 v = __ldg(inb + s0 * 32 + fl);
                a0 += v.x; a1 += v.y;
            }
            for (; e + 4 <= r1; e += 4) {
                int4 s4 = *(const int4*)(es + e);
                float2 v0 = __ldg(inb + s4.x * 32 + fl);
                float2 v1 = __ldg(inb + s4.y * 32 + fl);
                float2 v2 = __ldg(inb + s4.z * 32 + fl);
                float2 v3 = __ldg(inb + s4.w * 32 + fl);
                a0 += (v0.x + v1.x) + (v2.x + v3.x);
                a1 += (v0.y + v1.y) + (v2.y + v3.y);
            }
            for (; e < r1; e++) {
                int s0 = __ldg(es + e);
                float2 v = __ldg(inb + s0 * 32 + fl);
                a0 += v.x; a1 += v.y;
            }
            float si = g_rs_in[b * NN + n0 + m];
            float2 st; st.x = a0 * si; st.y = a1 * si;
            int sw = ((m >> 2) & 7) << 2;
            *(float2*)&sT[m * 64 + ((2 * fl) ^ sw)] = st;
        }
    }
    __syncthreads();

    // ---- GEMM: warp tile = nodes [mt*16, +16) x feats [ft*32, +32) ----
    {
        int mt = w >> 1, ft = w & 1;
        int ng = lane >> 3, qg = lane & 7;
        int nb = mt * 16 + ng * 4;
        int q0 = ft * 32 + qg * 4;
        int sx = ((nb >> 2) & 7) << 2;                // node-group swizzle
        int swz = (qg & 7) << 2;                      // w swizzle ((q0>>2)&7 == qg)

        unsigned long long acc01[4], acc23[4];
#pragma unroll
        for (int i = 0; i < 4; i++) { acc01[i] = 0ull; acc23[i] = 0ull; }

#pragma unroll
        for (int k0 = 0; k0 < 64; k0 += 4) {
            float4 wf[4];
            int kw = k0 ^ swz;
#pragma unroll
            for (int j = 0; j < 4; j++)
                wf[j] = *(const float4*)&sWt[(q0 + j) * 64 + kw];
            unsigned long long wp01[4], wp23[4];
#pragma unroll
            for (int kk = 0; kk < 4; kk++) {
                const float* w0 = (const float*)&wf[0];
                const float* w1 = (const float*)&wf[1];
                const float* w2 = (const float*)&wf[2];
                const float* w3 = (const float*)&wf[3];
                wp01[kk] = pk2(w0[kk], w1[kk]);
                wp23[kk] = pk2(w2[kk], w3[kk]);
            }
            int kx = k0 ^ sx;
#pragma unroll
            for (int i = 0; i < 4; i++) {
                float4 xf = *(const float4*)&sT[(nb + i) * 64 + kx];
                const float* xp = (const float*)&xf;
#pragma unroll
                for (int kk = 0; kk < 4; kk++) {
                    unsigned long long xx = pk2(xp[kk], xp[kk]);
                    acc01[i] = fma2(wp01[kk], xx, acc01[i]);
                    acc23[i] = fma2(wp23[kk], xx, acc23[i]);
                }
            }
        }

        // ---- epilogue ----
        float4 bv = __ldg((const float4*)(bias + q0));
#pragma unroll
        for (int i = 0; i < 4; i++) {
            int n = n0 + nb + i;
            float o0, o1, o2, o3;
            upk2(acc01[i], o0, o1);
            upk2(acc23[i], o2, o3);
            o0 += bv.x; o1 += bv.y; o2 += bv.z; o3 += bv.w;
            if (!phase) {
                float rs = __ldg(&g_rs_out[b * NN + n]);
                o0 = fmaxf(o0, 0.f) * rs; o1 = fmaxf(o1, 0.f) * rs;
                o2 = fmaxf(o2, 0.f) * rs; o3 = fmaxf(o3, 0.f) * rs;
            }
            float4 ov; ov.x = o0; ov.y = o1; ov.z = o2; ov.w = o3;
            *(float4*)(out + ((size_t)b * NN + n) * FF + q0) = ov;
        }
    }
}

// ---------------- BN stats / coef / final ----------------

__global__ __launch_bounds__(256) void k_bnstats() {
    int tid = blockIdx.x * 256 + threadIdx.x;
    int stride = gridDim.x * 256;
    const float4* h = (const float4*)g_h2;
    float4 s = make_float4(0.f, 0.f, 0.f, 0.f);
    float4 q = make_float4(0.f, 0.f, 0.f, 0.f);
    for (int i = tid; i < BB * NN * FF / 4; i += stride) {
        float4 v = __ldg(h + i);
        s.x += v.x; s.y += v.y; s.z += v.z; s.w += v.w;
        q.x = fmaf(v.x, v.x, q.x); q.y = fmaf(v.y, v.y, q.y);
        q.z = fmaf(v.z, v.z, q.z); q.w = fmaf(v.w, v.w, q.w);
    }
    int f0 = (tid & 15) * 4;
    __shared__ float sh[128];
    if (threadIdx.x < 128) sh[threadIdx.x] = 0.f;
    __syncthreads();
    atomicAdd(&sh[f0 + 0], s.x); atomicAdd(&sh[f0 + 1], s.y);
    atomicAdd(&sh[f0 + 2], s.z); atomicAdd(&sh[f0 + 3], s.w);
    atomicAdd(&sh[64 + f0 + 0], q.x); atomicAdd(&sh[64 + f0 + 1], q.y);
    atomicAdd(&sh[64 + f0 + 2], q.z); atomicAdd(&sh[64 + f0 + 3], q.w);
    __syncthreads();
    if (threadIdx.x < 128) atomicAdd(&g_bn_sum[threadIdx.x], sh[threadIdx.x]);
}

__global__ void k_bncoef(const float* __restrict__ gamma, const float* __restrict__ beta,
                         const float* __restrict__ lin_b, float* __restrict__ out) {
    int t = threadIdx.x;
    if (t < 64) {
        const float inv_n = 1.0f / (float)(BB * NN);
        float s  = g_bn_sum[t];
        float s2 = g_bn_sum[64 + t];
        float mean = s * inv_n;
        float var  = s2 * inv_n - mean * mean;
        float scale = gamma[t] * rsqrtf(var + BN_EPS);
        g_bn_coef[t]      = scale;
        g_bn_coef[64 + t] = beta[t] - mean * scale;
        g_bn_sum[t] = 0.0f;
        g_bn_sum[64 + t] = 0.0f;
    }
    if (t < 80) out[t] = lin_b[t % CC];
}

__global__ __launch_bounds__(256) void k_final(const float* __restrict__ linW,
                                               float* __restrict__ out) {
    __shared__ float cf[128];
    if (threadIdx.x < 128) cf[threadIdx.x] = g_bn_coef[threadIdx.x];
    __syncthreads();

    int tid = blockIdx.x * 256 + threadIdx.x;
    int stride = gridDim.x * 256;
    const int NI4 = NN * FF / 4;
    float acc[BB][CC];
#pragma unroll
    for (int b = 0; b < BB; b++)
#pragma unroll
        for (int c = 0; c < CC; c++) acc[b][c] = 0.f;

    const float4* h4 = (const float4*)g_h2;
    const float4* w4 = (const float4*)linW;
    for (int i = tid; i < NI4; i += stride) {
        int f0 = (i & 15) * 4;
        float4 sc  = *(const float4*)&cf[f0];
        float4 sh4 = *(const float4*)&cf[64 + f0];
        float4 hv[BB];
#pragma unroll
        for (int b = 0; b < BB; b++) {
            float4 v = __ldg(h4 + (size_t)b * NI4 + i);
            hv[b].x = fmaf(v.x, sc.x, sh4.x);
            hv[b].y = fmaf(v.y, sc.y, sh4.y);
            hv[b].z = fmaf(v.z, sc.z, sh4.z);
            hv[b].w = fmaf(v.w, sc.w, sh4.w);
        }
#pragma unroll
        for (int c = 0; c < CC; c++) {
            float4 w = __ldg(w4 + (size_t)c * NI4 + i);
#pragma unroll
            for (int b = 0; b < BB; b++) {
                float t0 = fmaf(hv[b].x, w.x, hv[b].y * w.y);
                float t1 = fmaf(hv[b].z, w.z, hv[b].w * w.w);
                acc[b][c] += t0 + t1;
            }
        }
    }
#pragma unroll
    for (int b = 0; b < BB; b++)
#pragma unroll
        for (int c = 0; c < CC; c++)
#pragma unroll
            for (int off = 16; off > 0; off >>= 1)
                acc[b][c] += __shfl_xor_sync(0xFFFFFFFFu, acc[b][c], off);

    __shared__ float part[8][80];
    int w = threadIdx.x >> 5, lane = threadIdx.x & 31;
    if (lane == 0) {
#pragma unroll
        for (int b = 0; b < BB; b++)
#pragma unroll
            for (int c = 0; c < CC; c++) part[w][b * CC + c] = acc[b][c];
    }
    __syncthreads();
    int t = threadIdx.x;
    if (t < 80) {
        float s = 0.f;
#pragma unroll
        for (int ww = 0; ww < 8; ww++) s += part[ww][t];
        atomicAdd(&out[t], s);
    }
}

// ---------------- launch ----------------
extern "C" void kernel_launch(void* const* d_in, const int* in_sizes, int n_in,
                              void* d_out, int out_size) {
    const float* x     = (const float*)d_in[0];
    const int*   esrc  = (const int*)  d_in[1];
    const int*   edst  = (const int*)  d_in[2];
    const float* W1    = (const float*)d_in[3];
    const float* b1    = (const float*)d_in[4];
    const float* W2    = (const float*)d_in[5];
    const float* b2    = (const float*)d_in[6];
    const float* gamma = (const float*)d_in[7];
    const float* beta  = (const float*)d_in[8];
    const float* linW  = (const float*)d_in[9];
    const float* linb  = (const float*)d_in[10];
    float* out = (float*)d_out;

    cudaFuncSetAttribute(k_conv, cudaFuncAttributeMaxDynamicSharedMemorySize, SMEM_CONV);

    k_degree <<<(BB * EE / 4) / 256, 256>>>((const int4*)esrc, (const int4*)edst);
    k_scan   <<<BB, 1024>>>();
    k_fill   <<<(BB * EE / 4) / 256, 256>>>((const int4*)esrc, (const int4*)edst,
                                            (const float4*)x);
    k_conv   <<<BB * (NN / 256), 1024, SMEM_CONV>>>(W1, b1, 0);  // idx 3 -> profiled
    k_conv   <<<BB * (NN / 256), 1024, SMEM_CONV>>>(W2, b2, 1);
    k_bnstats<<<256, 256>>>();
    k_bncoef <<<1, 128>>>(gamma, beta, linb, out);
    k_final  <<<296, 256>>>(linW, out);
}